// round 1
// baseline (speedup 1.0000x reference)
#include <cuda_runtime.h>
#include <math.h>

// Problem constants
#define Bb   8
#define Tt   2048
#define Hh   2048
#define Nn   100000
#define Pp   512
#define TOPK 10

typedef unsigned long long ull;

// ---------------- scratch (device globals; no allocations) ----------------
__device__ float g_part[Bb*16*Hh];      // partial T-sums: [b][chunk16][h]
__device__ float g_query[Bb*Hh];        // mean over T
__device__ float g_q[Bb*Pp];            // query @ Wq^T + bq
__device__ float g_sbk[Bb];             // q . bk
__device__ float g_qkpart[8*Bb*Hh];     // p-chunked partials of q @ Wk
__device__ float g_qkD[Bb*Hh];          // qk in warp-contiguous [i][q][lane][4] layout (64KB)
__device__ float g_scores[Bb*Nn];       // confidence-scaled scores
__device__ int   g_topidx[Bb*TOPK];
__device__ float g_gi[Bb*2*Hh];         // concat(query, mem_summary)
__device__ float g_gate[Bb*Hh];
__device__ float g_h1[Bb*Hh];
__device__ float g_mi[Bb*Hh];

// ---------------- f32x2 helpers ----------------
__device__ __forceinline__ ull pk2(float a, float b) {
    ull r; asm("mov.b64 %0,{%1,%2};" : "=l"(r) : "f"(a), "f"(b)); return r;
}
__device__ __forceinline__ void up2(ull v, float& a, float& b) {
    asm("mov.b64 {%0,%1},%2;" : "=f"(a), "=f"(b) : "l"(v));
}
__device__ __forceinline__ ull fma2(ull a, ull b, ull c) {
    ull d; asm("fma.rn.f32x2 %0,%1,%2,%3;" : "=l"(d) : "l"(a), "l"(b), "l"(c)); return d;
}

// ---------------- K1: partial sums over T (deterministic 2-stage mean) ----------------
__global__ void __launch_bounds__(256) k_partial(const float* __restrict__ x) {
    int b = blockIdx.x >> 1, hseg = blockIdx.x & 1, chunk = blockIdx.y;
    const float4* xp = (const float4*)x
        + ((size_t)(b*Tt + chunk*128) * Hh + hseg*1024) / 4 + threadIdx.x;
    float4 s = make_float4(0.f,0.f,0.f,0.f);
#pragma unroll 8
    for (int t = 0; t < 128; t++) {
        float4 v = __ldcs(xp + (size_t)t * (Hh/4));
        s.x += v.x; s.y += v.y; s.z += v.z; s.w += v.w;
    }
    ((float4*)g_part)[(b*16 + chunk)*(Hh/4) + hseg*256 + threadIdx.x] = s;
}

// ---------------- K2: finalize query mean ----------------
__global__ void __launch_bounds__(256) k_query() {
    int id = blockIdx.x*256 + threadIdx.x;     // 0..4095 float4s (B*H/4)
    int b = id >> 9, h4 = id & 511;
    float4 s = make_float4(0.f,0.f,0.f,0.f);
#pragma unroll
    for (int c = 0; c < 16; c++) {
        float4 v = ((const float4*)g_part)[(b*16 + c)*512 + h4];
        s.x += v.x; s.y += v.y; s.z += v.z; s.w += v.w;
    }
    const float inv = 1.0f / (float)Tt;
    s.x *= inv; s.y *= inv; s.z *= inv; s.w *= inv;
    ((float4*)g_query)[b*512 + h4] = s;
}

// ---------------- K3: q = query @ Wq^T + bq  (warp per output) ----------------
__global__ void __launch_bounds__(256) k_qproj(const float* __restrict__ Wq,
                                               const float* __restrict__ bq) {
    int lane = threadIdx.x & 31, warp = threadIdx.x >> 5;
    int o = blockIdx.x*8 + warp, b = blockIdx.y;
    const float4* w  = (const float4*)Wq + (size_t)o*512;
    const float4* qu = (const float4*)g_query + (size_t)b*512;
    float s = 0.f;
    for (int i = lane; i < 512; i += 32) {
        float4 a = __ldg(w + i), c = qu[i];
        s += a.x*c.x + a.y*c.y + a.z*c.z + a.w*c.w;
    }
#pragma unroll
    for (int off = 16; off; off >>= 1) s += __shfl_xor_sync(0xffffffffu, s, off);
    if (lane == 0) g_q[b*Pp + o] = s + bq[o];
}

// ---------------- K3b: sbk[b] = q[b] . bk ----------------
__global__ void __launch_bounds__(256) k_sbk(const float* __restrict__ bk) {
    int lane = threadIdx.x & 31, b = threadIdx.x >> 5;
    float s = 0.f;
    for (int i = lane; i < Pp; i += 32) s += g_q[b*Pp + i] * bk[i];
#pragma unroll
    for (int off = 16; off; off >>= 1) s += __shfl_xor_sync(0xffffffffu, s, off);
    if (lane == 0) g_sbk[b] = s;
}

// ---------------- K4a: qk partials over p-chunks (qk = q @ Wk) ----------------
__global__ void __launch_bounds__(128) k_qk_part(const float* __restrict__ Wk) {
    __shared__ float qs[512];                       // [b*64 + p]
    int p0 = blockIdx.y * 64;
    for (int z = threadIdx.x; z < 512; z += 128)
        qs[z] = g_q[(z >> 6)*Pp + p0 + (z & 63)];
    __syncthreads();
    int h = blockIdx.x*128 + threadIdx.x;
    float acc[8] = {0.f,0.f,0.f,0.f,0.f,0.f,0.f,0.f};
#pragma unroll 8
    for (int p = 0; p < 64; p++) {
        float w = __ldg(&Wk[(size_t)(p0 + p)*Hh + h]);
#pragma unroll
        for (int b = 0; b < 8; b++) acc[b] += qs[b*64 + p] * w;
    }
#pragma unroll
    for (int b = 0; b < 8; b++) g_qkpart[(blockIdx.y*8 + b)*Hh + h] = acc[b];
}

// ---------------- K4b: finish qk and scatter to warp-contiguous qkD layout ----------------
// logical qk[b][h] -> qkD[((i*8 + 2*hh + (b>>2))*32 + l)*4 + (b&3)]
// where c = h/4, i = c/32, l = c%32, hh = h%4
__global__ void __launch_bounds__(256) k_qk_finish() {
    int h = blockIdx.x*256 + threadIdx.x;
    int c = h >> 2, i = c >> 5, l = c & 31, hh = h & 3;
#pragma unroll
    for (int b = 0; b < 8; b++) {
        float s = 0.f;
#pragma unroll
        for (int pc = 0; pc < 8; pc++) s += g_qkpart[(pc*8 + b)*Hh + h];
        g_qkD[((i*8 + 2*hh + (b >> 2))*32 + l)*4 + (b & 3)] = s;
    }
}

// ---------------- K5: scores = (qk @ keys^T + sbk) * conf  (the big one) ----------------
// 8 warps/block, 4 rows per warp, f32x2 packed FMAs, keys via L2-only loads,
// qkD via L1-resident coalesced loads.
__global__ void __launch_bounds__(256) k_scores(const float* __restrict__ keys,
                                                const float* __restrict__ conf) {
    const int lane = threadIdx.x & 31;
    const int warp = threadIdx.x >> 5;
    const float4* __restrict__ qkD4 = (const float4*)g_qkD;
    for (int tile = blockIdx.x; tile < (Nn/32); tile += gridDim.x) {
        int n0 = tile*32 + warp*4;                   // Nn % 32 == 0: no tail
        const float4* k0 = (const float4*)keys + (size_t)n0 * (Hh/4);
        ull acc[4][4];
#pragma unroll
        for (int r = 0; r < 4; r++)
#pragma unroll
            for (int j = 0; j < 4; j++) acc[r][j] = 0ull;
#pragma unroll 4
        for (int i = 0; i < 16; i++) {
            float4 kv[4];
#pragma unroll
            for (int r = 0; r < 4; r++)
                kv[r] = __ldcg(k0 + (size_t)r*(Hh/4) + i*32 + lane);
#pragma unroll
            for (int hh = 0; hh < 4; hh++) {
                ull kd[4];
#pragma unroll
                for (int r = 0; r < 4; r++) {
                    float cc = (hh == 0) ? kv[r].x : (hh == 1) ? kv[r].y
                             : (hh == 2) ? kv[r].z : kv[r].w;
                    kd[r] = pk2(cc, cc);
                }
#pragma unroll
                for (int s = 0; s < 2; s++) {
                    float4 qv = __ldg(&qkD4[(i*8 + hh*2 + s)*32 + lane]);
                    ull qlo = pk2(qv.x, qv.y), qhi = pk2(qv.z, qv.w);
#pragma unroll
                    for (int r = 0; r < 4; r++) {
                        acc[r][2*s]   = fma2(kd[r], qlo, acc[r][2*s]);
                        acc[r][2*s+1] = fma2(kd[r], qhi, acc[r][2*s+1]);
                    }
                }
            }
        }
        // unpack: acc[r][j] holds batch pair (2j, 2j+1)
        float a[4][8];
#pragma unroll
        for (int r = 0; r < 4; r++)
#pragma unroll
            for (int j = 0; j < 4; j++) up2(acc[r][j], a[r][2*j], a[r][2*j+1]);
#pragma unroll
        for (int off = 16; off; off >>= 1)
#pragma unroll
            for (int r = 0; r < 4; r++)
#pragma unroll
                for (int bb = 0; bb < 8; bb++)
                    a[r][bb] += __shfl_xor_sync(0xffffffffu, a[r][bb], off);
        if (lane == 0) {
#pragma unroll
            for (int r = 0; r < 4; r++) {
                int n = n0 + r;
                float cf = conf[n];
#pragma unroll
                for (int bb = 0; bb < 8; bb++)
                    g_scores[(size_t)bb*Nn + n] = (a[r][bb] + g_sbk[bb]) * cf;
            }
        }
    }
}

// ---------------- K6: top-k indices per batch (set semantics; deterministic) ----------------
__global__ void __launch_bounds__(256) k_topk() {
    int b = blockIdx.x, tid = threadIdx.x;
    float v[TOPK]; int ix[TOPK];
#pragma unroll
    for (int j = 0; j < TOPK; j++) { v[j] = -3.4e38f; ix[j] = 0x7fffffff; }
    const float* sc = g_scores + (size_t)b*Nn;
    for (int n = tid; n < Nn; n += 256) {
        float s = sc[n];
        if (s > v[TOPK-1]) {
            v[TOPK-1] = s; ix[TOPK-1] = n;
#pragma unroll
            for (int j = TOPK-1; j > 0; j--) {
                bool sw = (v[j] > v[j-1]) || (v[j] == v[j-1] && ix[j] < ix[j-1]);
                if (sw) {
                    float tv = v[j]; v[j] = v[j-1]; v[j-1] = tv;
                    int   ti = ix[j]; ix[j] = ix[j-1]; ix[j-1] = ti;
                }
            }
        }
    }
    __shared__ float sv[256*TOPK];
    __shared__ int   si[256*TOPK];
    __shared__ float rv[256]; __shared__ int ri[256]; __shared__ int rp[256];
#pragma unroll
    for (int j = 0; j < TOPK; j++) { sv[tid*TOPK + j] = v[j]; si[tid*TOPK + j] = ix[j]; }
    __syncthreads();
    for (int k = 0; k < TOPK; k++) {
        float bv = -3.4e38f; int bi = 0x7fffffff, bp = 0;
        for (int j = tid; j < 256*TOPK; j += 256) {
            float cv = sv[j]; int ci = si[j];
            if (cv > bv || (cv == bv && ci < bi)) { bv = cv; bi = ci; bp = j; }
        }
        rv[tid] = bv; ri[tid] = bi; rp[tid] = bp;
        __syncthreads();
        for (int st = 128; st > 0; st >>= 1) {
            if (tid < st) {
                float cv = rv[tid+st]; int ci = ri[tid+st];
                if (cv > rv[tid] || (cv == rv[tid] && ci < ri[tid])) {
                    rv[tid] = cv; ri[tid] = ci; rp[tid] = rp[tid+st];
                }
            }
            __syncthreads();
        }
        if (tid == 0) { g_topidx[b*TOPK + k] = ri[0]; sv[rp[0]] = -3.4e38f; }
        __syncthreads();
    }
}

// ---------------- K7: gate_input = concat(query, mean of retrieved keys) ----------------
__global__ void __launch_bounds__(256) k_gi(const float* __restrict__ keys) {
    int b = blockIdx.x;
    int idx[TOPK];
#pragma unroll
    for (int j = 0; j < TOPK; j++) idx[j] = g_topidx[b*TOPK + j];
    for (int h4 = threadIdx.x; h4 < 512; h4 += 256) {
        ((float4*)g_gi)[b*1024 + h4] = ((const float4*)g_query)[b*512 + h4];
        float4 s = make_float4(0.f,0.f,0.f,0.f);
#pragma unroll
        for (int j = 0; j < TOPK; j++) {
            float4 kv = __ldg((const float4*)keys + (size_t)idx[j]*(Hh/4) + h4);
            s.x += kv.x; s.y += kv.y; s.z += kv.z; s.w += kv.w;
        }
        const float inv = 1.0f / (float)TOPK;
        s.x *= inv; s.y *= inv; s.z *= inv; s.w *= inv;
        ((float4*)g_gi)[b*1024 + 512 + h4] = s;
    }
}

// ---------------- K8: gate = sigmoid(gi@Wg^T+bg), h1 = gelu(gi@Wm1^T+bm1) ----------------
__global__ void __launch_bounds__(256) k_mlp1(const float* __restrict__ Wg,
                                              const float* __restrict__ bg,
                                              const float* __restrict__ Wm1,
                                              const float* __restrict__ bm1) {
    int lane = threadIdx.x & 31, warp = threadIdx.x >> 5;
    int wg = blockIdx.x*8 + warp;
    int which = wg >> 11, o = wg & 2047;
    const float4* W = (const float4*)(which ? Wm1 : Wg) + (size_t)o*1024;
    float acc[8] = {0.f,0.f,0.f,0.f,0.f,0.f,0.f,0.f};
    for (int i = lane; i < 1024; i += 32) {
        float4 w = __ldcs(W + i);
#pragma unroll
        for (int b = 0; b < 8; b++) {
            float4 g = __ldg((const float4*)g_gi + b*1024 + i);
            acc[b] += w.x*g.x + w.y*g.y + w.z*g.z + w.w*g.w;
        }
    }
#pragma unroll
    for (int off = 16; off; off >>= 1)
#pragma unroll
        for (int b = 0; b < 8; b++) acc[b] += __shfl_xor_sync(0xffffffffu, acc[b], off);
    if (lane == 0) {
        float bias = which ? bm1[o] : bg[o];
#pragma unroll
        for (int b = 0; b < 8; b++) {
            float z = acc[b] + bias;
            if (which) g_h1[b*Hh + o] = 0.5f*z*(1.0f + erff(z*0.70710678118654752440f));
            else       g_gate[b*Hh + o] = 1.0f / (1.0f + expf(-z));
        }
    }
}

// ---------------- K9: mem_integrated = h1 @ Wm2^T + bm2 ----------------
__global__ void __launch_bounds__(256) k_mi(const float* __restrict__ Wm2,
                                            const float* __restrict__ bm2) {
    int lane = threadIdx.x & 31, warp = threadIdx.x >> 5;
    int o = blockIdx.x*8 + warp;
    const float4* W = (const float4*)Wm2 + (size_t)o*512;
    float acc[8] = {0.f,0.f,0.f,0.f,0.f,0.f,0.f,0.f};
    for (int i = lane; i < 512; i += 32) {
        float4 w = __ldcs(W + i);
#pragma unroll
        for (int b = 0; b < 8; b++) {
            float4 g = __ldg((const float4*)g_h1 + b*512 + i);
            acc[b] += w.x*g.x + w.y*g.y + w.z*g.z + w.w*g.w;
        }
    }
#pragma unroll
    for (int off = 16; off; off >>= 1)
#pragma unroll
        for (int b = 0; b < 8; b++) acc[b] += __shfl_xor_sync(0xffffffffu, acc[b], off);
    if (lane == 0) {
        float bias = bm2[o];
#pragma unroll
        for (int b = 0; b < 8; b++) g_mi[b*Hh + o] = acc[b] + bias;
    }
}

// ---------------- K10: y = x + gate*mi; LayerNorm over H ----------------
__global__ void __launch_bounds__(256) k_final(const float* __restrict__ x,
                                               const float* __restrict__ gamma,
                                               const float* __restrict__ beta,
                                               float* __restrict__ out) {
    int row = blockIdx.x;            // b*T + t
    int b = row >> 11;
    const float4* xr = (const float4*)x + (size_t)row*512;
    float4* orow = (float4*)out + (size_t)row*512;
    int i0 = threadIdx.x, i1 = threadIdx.x + 256;
    float4 x0 = __ldcs(xr + i0), x1 = __ldcs(xr + i1);
    float4 ga = __ldg((const float4*)g_gate + b*512 + i0);
    float4 gb = __ldg((const float4*)g_gate + b*512 + i1);
    float4 ma = __ldg((const float4*)g_mi   + b*512 + i0);
    float4 mb = __ldg((const float4*)g_mi   + b*512 + i1);
    float4 y0, y1;
    y0.x = x0.x + ga.x*ma.x; y0.y = x0.y + ga.y*ma.y;
    y0.z = x0.z + ga.z*ma.z; y0.w = x0.w + ga.w*ma.w;
    y1.x = x1.x + gb.x*mb.x; y1.y = x1.y + gb.y*mb.y;
    y1.z = x1.z + gb.z*mb.z; y1.w = x1.w + gb.w*mb.w;
    float s  = y0.x + y0.y + y0.z + y0.w + y1.x + y1.y + y1.z + y1.w;
    float ss = y0.x*y0.x + y0.y*y0.y + y0.z*y0.z + y0.w*y0.w
             + y1.x*y1.x + y1.y*y1.y + y1.z*y1.z + y1.w*y1.w;
#pragma unroll
    for (int off = 16; off; off >>= 1) {
        s  += __shfl_xor_sync(0xffffffffu, s,  off);
        ss += __shfl_xor_sync(0xffffffffu, ss, off);
    }
    __shared__ float sh[16];
    int lane = threadIdx.x & 31, warp = threadIdx.x >> 5;
    if (lane == 0) { sh[warp] = s; sh[8 + warp] = ss; }
    __syncthreads();
    if (threadIdx.x < 32) {
        float a = (lane < 8) ? sh[lane] : 0.f;
        float c = (lane < 8) ? sh[8 + lane] : 0.f;
#pragma unroll
        for (int off = 4; off; off >>= 1) {
            a += __shfl_xor_sync(0xffffffffu, a, off);
            c += __shfl_xor_sync(0xffffffffu, c, off);
        }
        if (lane == 0) { sh[0] = a; sh[1] = c; }
    }
    __syncthreads();
    float mu  = sh[0] * (1.0f/2048.0f);
    float var = sh[1] * (1.0f/2048.0f) - mu*mu;
    float rstd = rsqrtf(var + 1e-5f);
    float4 gm0 = __ldg((const float4*)gamma + i0), gm1 = __ldg((const float4*)gamma + i1);
    float4 be0 = __ldg((const float4*)beta  + i0), be1 = __ldg((const float4*)beta  + i1);
    float4 o0, o1;
    o0.x = (y0.x - mu)*rstd*gm0.x + be0.x; o0.y = (y0.y - mu)*rstd*gm0.y + be0.y;
    o0.z = (y0.z - mu)*rstd*gm0.z + be0.z; o0.w = (y0.w - mu)*rstd*gm0.w + be0.w;
    o1.x = (y1.x - mu)*rstd*gm1.x + be1.x; o1.y = (y1.y - mu)*rstd*gm1.y + be1.y;
    o1.z = (y1.z - mu)*rstd*gm1.z + be1.z; o1.w = (y1.w - mu)*rstd*gm1.w + be1.w;
    orow[i0] = o0; orow[i1] = o1;
}

// ---------------- launch ----------------
extern "C" void kernel_launch(void* const* d_in, const int* in_sizes, int n_in,
                              void* d_out, int out_size) {
    const float* x     = (const float*)d_in[0];
    const float* keys  = (const float*)d_in[1];
    const float* conf  = (const float*)d_in[2];
    const float* Wq    = (const float*)d_in[3];
    const float* bq    = (const float*)d_in[4];
    const float* Wk    = (const float*)d_in[5];
    const float* bk    = (const float*)d_in[6];
    const float* Wg    = (const float*)d_in[7];
    const float* bg    = (const float*)d_in[8];
    const float* Wm1   = (const float*)d_in[9];
    const float* bm1   = (const float*)d_in[10];
    const float* Wm2   = (const float*)d_in[11];
    const float* bm2   = (const float*)d_in[12];
    const float* gamma = (const float*)d_in[13];
    const float* beta  = (const float*)d_in[14];
    float* out = (float*)d_out;

    k_partial  <<<dim3(16,16), 256>>>(x);
    k_query    <<<16, 256>>>();
    k_qproj    <<<dim3(64,8), 256>>>(Wq, bq);
    k_sbk      <<<1, 256>>>(bk);
    k_qk_part  <<<dim3(16,8), 128>>>(Wk);
    k_qk_finish<<<8, 256>>>();
    k_scores   <<<1184, 256>>>(keys, conf);
    k_topk     <<<8, 256>>>();
    k_gi       <<<8, 256>>>(keys);
    k_mlp1     <<<512, 256>>>(Wg, bg, Wm1, bm1);
    k_mi       <<<256, 256>>>(Wm2, bm2);
    k_final    <<<16384, 256>>>(x, gamma, beta, out);
}